// round 9
// baseline (speedup 1.0000x reference)
#include <cuda_runtime.h>
#include <math.h>
#include <stdint.h>

// ---------------- problem constants ----------------
#define Bsz     2
#define Hdim    256
#define Wdim    256
#define Cc      192
#define NHEADS  6
#define HID     768
#define TOK     (Bsz*Hdim*Wdim)      // 131072 tokens
#define NWIN    2048

// ---------------- scratch ----------------
__device__ float g_bufA[(size_t)TOK*Cc];    // xn / xn2
__device__ float g_bufB[(size_t)TOK*Cc];    // attention output (pre-proj)
__device__ float g_bufC[(size_t)TOK*Cc];    // x after attention residual
__device__ float g_bufD[(size_t)TOK*HID];   // q, later h1
__device__ float g_bufE[(size_t)TOK*HID];   // kv, later h

__device__ __forceinline__ float gelu_exact(float x) {
    return 0.5f * x * (1.0f + erff(x * 0.70710678118654752f));
}

__device__ __forceinline__ void cp_async16(uint32_t dst, const void* src) {
    asm volatile("cp.async.cg.shared.global [%0], [%1], 16;" :: "r"(dst), "l"(src));
}
__device__ __forceinline__ void cp_commit() {
    asm volatile("cp.async.commit_group;");
}
template<int N_>
__device__ __forceinline__ void cp_wait() {
    asm volatile("cp.async.wait_group %0;" :: "n"(N_));
}

// ---------------- LayerNorm ----------------
__global__ __launch_bounds__(256)
void ln_kernel(const float* __restrict__ x, const float* __restrict__ g,
               const float* __restrict__ b, float* __restrict__ out) {
    int warp = (blockIdx.x * blockDim.x + threadIdx.x) >> 5;
    int lane = threadIdx.x & 31;
    if (warp >= TOK) return;
    const float* xr = x + (size_t)warp * Cc;
    float v[6];
    float s = 0.f, s2 = 0.f;
#pragma unroll
    for (int j = 0; j < 6; j++) {
        v[j] = xr[lane + 32*j];
        s += v[j]; s2 += v[j]*v[j];
    }
#pragma unroll
    for (int o = 16; o; o >>= 1) {
        s  += __shfl_xor_sync(0xffffffffu, s,  o);
        s2 += __shfl_xor_sync(0xffffffffu, s2, o);
    }
    float mu  = s  * (1.f/Cc);
    float var = s2 * (1.f/Cc) - mu*mu;
    float r   = rsqrtf(var + 1e-5f);
    float* orow = out + (size_t)warp * Cc;
#pragma unroll
    for (int j = 0; j < 6; j++) {
        int c = lane + 32*j;
        orow[c] = (v[j]-mu)*r*g[c] + b[c];
    }
}

// ---------------- tf32 tensor-core GEMM, exact-width tiles (R8-proven) ----------------
#define BM 128
#define BK 16

template<int NTN, int EPI>
__global__ __launch_bounds__(256)
void mma_gemm(const float* __restrict__ A, const float* __restrict__ Wt,
              const float* __restrict__ bias, const float* __restrict__ res,
              float* __restrict__ C, int M, int N, int K) {
    constexpr int BN = NTN * 32;
    constexpr int SB = BN + 8;
    __shared__ float As[2][BM][20];    // [m][k], stride 20 (conflict-free)
    __shared__ float Bs[2][BK][SB];    // [k][n]

    const int tid  = threadIdx.x;
    const int lane = tid & 31;
    const int warp = tid >> 5;
    const int wm = (warp >> 2) * 64;
    const int wn = (warp & 3) * (NTN*8);
    const int m0 = blockIdx.y * BM;
    const int n0 = blockIdx.x * BN;
    const int gr = lane >> 2;
    const int gc = lane & 3;

    const uint32_t abase = (uint32_t)__cvta_generic_to_shared(&As[0][0][0]);
    const uint32_t bbase = (uint32_t)__cvta_generic_to_shared(&Bs[0][0][0]);

    float acc[4][NTN][4];
#pragma unroll
    for (int i = 0; i < 4; i++)
#pragma unroll
        for (int j = 0; j < NTN; j++)
#pragma unroll
            for (int t = 0; t < 4; t++) acc[i][j][t] = 0.f;

    const int niter = K / BK;

    auto load_stage = [&](int s, int it) {
        const int k0 = it * BK;
#pragma unroll
        for (int h = 0; h < 2; h++) {
            int f = tid + h*256;
            int row = f >> 2, c4 = (f & 3) * 4;
            cp_async16(abase + (uint32_t)((((s*BM + row)*20) + c4) * 4),
                       A + (size_t)(m0 + row)*K + k0 + c4);
        }
        for (int f = tid; f < 16*(BN/4); f += 256) {
            int k = f / (BN/4), c4 = (f % (BN/4)) * 4;
            cp_async16(bbase + (uint32_t)((((s*BK + k)*SB) + c4) * 4),
                       Wt + (size_t)(k0 + k)*N + n0 + c4);
        }
    };

    load_stage(0, 0);
    cp_commit();

    for (int it = 0; it < niter; it++) {
        if (it + 1 < niter) load_stage((it + 1) & 1, it + 1);
        cp_commit();
        cp_wait<1>();
        __syncthreads();

        const int s = it & 1;
#pragma unroll
        for (int ks = 0; ks < 2; ks++) {
            const int kb = ks * 8;
            unsigned af[4][4];
#pragma unroll
            for (int mt = 0; mt < 4; mt++) {
                int mr = wm + mt*16 + gr;
                af[mt][0] = __float_as_uint(As[s][mr    ][kb + gc    ]);
                af[mt][1] = __float_as_uint(As[s][mr + 8][kb + gc    ]);
                af[mt][2] = __float_as_uint(As[s][mr    ][kb + gc + 4]);
                af[mt][3] = __float_as_uint(As[s][mr + 8][kb + gc + 4]);
            }
            unsigned bf[NTN][2];
#pragma unroll
            for (int nt = 0; nt < NTN; nt++) {
                int nc = wn + nt*8 + gr;
                bf[nt][0] = __float_as_uint(Bs[s][kb + gc    ][nc]);
                bf[nt][1] = __float_as_uint(Bs[s][kb + gc + 4][nc]);
            }
#pragma unroll
            for (int mt = 0; mt < 4; mt++)
#pragma unroll
                for (int nt = 0; nt < NTN; nt++) {
                    asm volatile(
                        "mma.sync.aligned.m16n8k8.row.col.f32.tf32.tf32.f32 "
                        "{%0,%1,%2,%3}, {%4,%5,%6,%7}, {%8,%9}, {%0,%1,%2,%3};"
                        : "+f"(acc[mt][nt][0]), "+f"(acc[mt][nt][1]),
                          "+f"(acc[mt][nt][2]), "+f"(acc[mt][nt][3])
                        : "r"(af[mt][0]), "r"(af[mt][1]), "r"(af[mt][2]), "r"(af[mt][3]),
                          "r"(bf[nt][0]), "r"(bf[nt][1]));
                }
        }
        __syncthreads();
    }

    // ---- epilogue ----
#pragma unroll
    for (int mt = 0; mt < 4; mt++) {
#pragma unroll
        for (int nt = 0; nt < NTN; nt++) {
            int col = n0 + wn + nt*8 + gc*2;
#pragma unroll
            for (int hh = 0; hh < 2; hh++) {
                int row = m0 + wm + mt*16 + gr + hh*8;
                float v0 = acc[mt][nt][hh*2+0];
                float v1 = acc[mt][nt][hh*2+1];
                v0 += bias[col]; v1 += bias[col+1];
                if (EPI == 2) { v0 = gelu_exact(v0); v1 = gelu_exact(v1); }
                if (EPI == 3) {
                    const float* rr = res + (size_t)row*N + col;
                    v0 += rr[0]; v1 += rr[1];
                }
                *(float2*)(C + (size_t)row*N + col) = make_float2(v0, v1);
            }
        }
    }
}

// ---------------- fused windowed attention (smem-staged coalesced q) ----------------
// dynamic smem: sq[64][200] + sk[6*512] + sv[6*512]
#define ATTN_SMEM ((64*200 + 2*6*512) * 4)

__global__ __launch_bounds__(384, 2)
void attn_kernel(const float* __restrict__ qbuf, const float* __restrict__ kvbuf,
                 const float* __restrict__ bias_table, float* __restrict__ aw) {
    extern __shared__ float smem[];
    float* sq = smem;                 // 64 rows x 200
    float* sk = smem + 64*200;        // [h][kv][d]
    float* sv = sk + 6*512;

    const int wid = blockIdx.x;
    const int b  = wid >> 10;
    const int wy = (wid >> 5) & 31;
    const int wx = wid & 31;
    const int base = b*65536 + wy*8*256 + wx*8;
    const int tid = threadIdx.x;

    // ---- stage q coalesced: window rows come in 8 contiguous-token groups of 192 floats ----
    {
        const int half = tid / 192;           // 0 or 1
        const int c    = tid - half*192;
        for (int r = half; r < 64; r += 2) {
            int grow = base + (r >> 3)*256 + (r & 7);
            sq[r*200 + c] = qbuf[(size_t)grow*Cc + c];
        }
    }
    // ---- stage kv with PSA rearrange ----
    for (int ii = tid; ii < 2*16*192; ii += 384) {
        int sel = ii / (16*192);
        int rem = ii - sel*(16*192);
        int tok = rem / 192;
        int hd  = rem - tok*192;
        int i   = hd / 96;
        int j   = (hd / 48) & 1;
        int c48 = hd % 48;
        int p1 = tok >> 2, p2 = tok & 3;
        int grow = base + (p1*2 + i)*256 + (p2*2 + j);
        float val = kvbuf[(size_t)grow*96 + sel*48 + c48];
        float* dst = sel ? sv : sk;
        dst[(hd >> 5)*512 + tok*32 + (hd & 31)] = val;
    }
    __syncthreads();

    const int h  = tid / 64;
    const int qt = tid % 64;
    const int qr = qt >> 3, qc = qt & 7;
    const int qrow = base + qr*256 + qc;

    float q[32];
    const float* qp = sq + qt*200 + h*32;
#pragma unroll
    for (int d4 = 0; d4 < 8; d4++) {
        float4 t = *(const float4*)(qp + d4*4);
        q[d4*4+0]=t.x; q[d4*4+1]=t.y; q[d4*4+2]=t.z; q[d4*4+3]=t.w;
    }

    const float SCALE = 0.17677669529663687f;
    const int qr2 = qr >> 1, qc2 = qc >> 1;
    float sc[16];
    float m = -1e30f;
#pragma unroll
    for (int kv = 0; kv < 16; kv++) {
        const float* kp = sk + h*512 + kv*32;
        float dot = 0.f;
#pragma unroll
        for (int d = 0; d < 32; d++) dot += q[d]*kp[d];
        int kr = kv >> 2, kc = kv & 3;
        int rel = (qr2 - kr + 3)*7 + (qc2 - kc + 3);
        float s = dot*SCALE + bias_table[rel*NHEADS + h];
        sc[kv] = s;
        m = fmaxf(m, s);
    }
    float sum = 0.f;
#pragma unroll
    for (int kv = 0; kv < 16; kv++) { sc[kv] = __expf(sc[kv]-m); sum += sc[kv]; }
    float inv = 1.f/sum;
    float o[32];
#pragma unroll
    for (int d = 0; d < 32; d++) o[d] = 0.f;
#pragma unroll
    for (int kv = 0; kv < 16; kv++) {
        float p = sc[kv]*inv;
        const float* vp = sv + h*512 + kv*32;
#pragma unroll
        for (int d = 0; d < 32; d++) o[d] += p*vp[d];
    }
    float* op = aw + (size_t)qrow*Cc + h*32;
#pragma unroll
    for (int d4 = 0; d4 < 8; d4++) {
        *(float4*)(op + d4*4) = make_float4(o[d4*4+0],o[d4*4+1],o[d4*4+2],o[d4*4+3]);
    }
}

// ---------------- depthwise 5x5 conv branch ----------------
__global__ __launch_bounds__(256)
void dwconv_kernel(const float* __restrict__ h1, const float* __restrict__ dwk,
                   const float* __restrict__ dwb, float* __restrict__ out) {
    __shared__ float2 s[144][32];
    const int cb = blockIdx.z % 12;
    const int b  = blockIdx.z / 12;
    const int y0 = blockIdx.y * 8, x0 = blockIdx.x * 8;
    const int tid = threadIdx.x;

    for (int ii = tid; ii < 144*32; ii += 256) {
        int pix = ii >> 5, c2 = ii & 31;
        int py = pix / 12, px = pix % 12;
        int gy = y0 + py - 2, gx = x0 + px - 2;
        float2 v = make_float2(0.f, 0.f);
        if (gy >= 0 && gy < Hdim && gx >= 0 && gx < Wdim) {
            size_t row = (size_t)(b*65536 + gy*256 + gx);
            v = *(const float2*)(h1 + row*HID + cb*64 + c2*2);
        }
        s[pix][c2] = v;
    }
    __syncthreads();

    const int c2 = tid & 31;
    const int pq = tid >> 5;
    const int c0 = cb*64 + c2*2;

    float2 wk[25];
#pragma unroll
    for (int t = 0; t < 25; t++) {
        wk[t].x = dwk[(size_t)c0*25 + t];
        wk[t].y = dwk[(size_t)(c0+1)*25 + t];
    }
    float2 bb = make_float2(dwb[c0], dwb[c0+1]);

    float2 win[5][5];
#pragma unroll
    for (int dx = 0; dx < 5; dx++)
#pragma unroll
        for (int dy = 0; dy < 5; dy++)
            win[dx][dy] = s[(pq+dy)*12 + dx][c2];

#pragma unroll
    for (int px = 0; px < 8; px++) {
        float2 acc = make_float2(0.f, 0.f);
#pragma unroll
        for (int dy = 0; dy < 5; dy++)
#pragma unroll
            for (int dx = 0; dx < 5; dx++) {
                float2 v = win[dx][dy];
                float2 w = wk[dy*5+dx];
                acc.x += v.x*w.x;
                acc.y += v.y*w.y;
            }
        float2 center = win[2][2];
        float2 r;
        r.x = center.x + gelu_exact(acc.x + bb.x);
        r.y = center.y + gelu_exact(acc.y + bb.y);
        size_t row = (size_t)(b*65536 + (y0+pq)*256 + (x0+px));
        *(float2*)(out + row*HID + c0) = r;
        if (px < 7) {
#pragma unroll
            for (int dx = 0; dx < 4; dx++)
#pragma unroll
                for (int dy = 0; dy < 5; dy++)
                    win[dx][dy] = win[dx+1][dy];
#pragma unroll
            for (int dy = 0; dy < 5; dy++)
                win[4][dy] = s[(pq+dy)*12 + (px+5)][c2];
        }
    }
}

// ---------------- launch ----------------
extern "C" void kernel_launch(void* const* d_in, const int* in_sizes, int n_in,
                              void* d_out, int out_size) {
    const float* x          = (const float*)d_in[0];
    const float* g1         = (const float*)d_in[1];
    const float* be1        = (const float*)d_in[2];
    const float* wq         = (const float*)d_in[3];
    const float* bq         = (const float*)d_in[4];
    const float* wkv        = (const float*)d_in[5];
    const float* bkv        = (const float*)d_in[6];
    const float* bias_table = (const float*)d_in[7];
    const float* wproj      = (const float*)d_in[8];
    const float* bproj      = (const float*)d_in[9];
    const float* g2         = (const float*)d_in[10];
    const float* be2        = (const float*)d_in[11];
    const float* w1f        = (const float*)d_in[12];
    const float* b1f        = (const float*)d_in[13];
    const float* dwk        = (const float*)d_in[14];
    const float* dwb        = (const float*)d_in[15];
    const float* w2f        = (const float*)d_in[16];
    const float* b2f        = (const float*)d_in[17];
    float* out = (float*)d_out;

    float *bufA, *bufB, *bufC, *bufD, *bufE;
    cudaGetSymbolAddress((void**)&bufA, g_bufA);
    cudaGetSymbolAddress((void**)&bufB, g_bufB);
    cudaGetSymbolAddress((void**)&bufC, g_bufC);
    cudaGetSymbolAddress((void**)&bufD, g_bufD);
    cudaGetSymbolAddress((void**)&bufE, g_bufE);

    cudaFuncSetAttribute(attn_kernel, cudaFuncAttributeMaxDynamicSharedMemorySize, ATTN_SMEM);

    // 1. LN1
    ln_kernel<<<TOK/8, 256>>>(x, g1, be1, bufA);
    // 2. q = xn @ wq + bq           (N=192 = 2 x 96, exact)
    mma_gemm<3,1><<<dim3(2, TOK/BM), 256>>>(bufA, wq, bq, nullptr, bufD, TOK, 192, 192);
    // 3. kv = xn @ wkv + bkv        (N=96, exact)
    mma_gemm<3,1><<<dim3(1, TOK/BM), 256>>>(bufA, wkv, bkv, nullptr, bufE, TOK, 96, 192);
    // 4. attention
    attn_kernel<<<NWIN, 384, ATTN_SMEM>>>(bufD, bufE, bias_table, bufB);
    // 5. x2 = x + aw @ wproj + bproj
    mma_gemm<3,3><<<dim3(2, TOK/BM), 256>>>(bufB, wproj, bproj, x, bufC, TOK, 192, 192);
    // 6. LN2
    ln_kernel<<<TOK/8, 256>>>(bufC, g2, be2, bufA);
    // 7. h1 = gelu(xn2 @ w1f + b1f)   (N=768 = 8 x 96, exact)
    mma_gemm<3,2><<<dim3(8, TOK/BM), 256>>>(bufA, w1f, b1f, nullptr, bufD, TOK, HID, 192);
    // 8. h = h1 + gelu(dwconv(h1)+dwb)
    dwconv_kernel<<<dim3(32, 32, Bsz*12), 256>>>(bufD, dwk, dwb, bufE);
    // 9. out = x2 + h @ w2f + b2f     (N=192 = 2 x 96, K=768, exact)
    mma_gemm<3,3><<<dim3(2, TOK/BM), 256>>>(bufE, w2f, b2f, bufC, out, TOK, 192, HID);
}